// round 1
// baseline (speedup 1.0000x reference)
#include <cuda_runtime.h>
#include <math.h>

// Problem constants
#define BATCH   4
#define N_Q     2048
#define M_KV    1024
#define QD      1024
#define CD      768
#define HEADS   8
#define DHEAD   64
#define INNER   (HEADS * DHEAD)   // 512
#define ATT_SCALE 0.125f          // 1/sqrt(64)

// Device-global scratch (allocation-free per harness rules)
__device__ float g_Q[(size_t)BATCH * N_Q * INNER];   // 16 MB
__device__ float g_K[(size_t)BATCH * M_KV * INNER];  //  8 MB
__device__ float g_V[(size_t)BATCH * M_KV * INNER];  //  8 MB
__device__ float g_O[(size_t)BATCH * N_Q * INNER];   // 16 MB

// ---------------------------------------------------------------------------
// Tiled SGEMM: C[M,N] = A[M,K] * B[K,N] (+ bias[N] if bias != nullptr)
// 128x128 block tile, BK=8, 256 threads, 8x8 per-thread register tile.
// Requires M%128==0, N%128==0, K%8==0 (true for all four GEMMs here).
// ---------------------------------------------------------------------------
__global__ void __launch_bounds__(256) sgemm_kernel(
    const float* __restrict__ A, const float* __restrict__ Bm,
    const float* __restrict__ bias, float* __restrict__ C,
    int M, int N, int K)
{
    __shared__ float As[8][128];   // transposed A tile: As[k][m]
    __shared__ float Bs[8][128];   // Bs[k][n]

    const int tid = threadIdx.x;
    const int bm = blockIdx.y * 128;
    const int bn = blockIdx.x * 128;
    const int ty = tid >> 4;       // 0..15  -> rows ty*8..ty*8+7
    const int tx = tid & 15;       // 0..15  -> cols tx*8..tx*8+7

    float acc[8][8];
#pragma unroll
    for (int i = 0; i < 8; i++)
#pragma unroll
        for (int j = 0; j < 8; j++) acc[i][j] = 0.0f;

    const int arow = tid >> 1;           // 0..127
    const int acol = (tid & 1) * 4;      // 0 or 4
    const int brow = tid >> 5;           // 0..7
    const int bcol = (tid & 31) * 4;     // 0..124

    const float* Aptr = A + (size_t)(bm + arow) * K + acol;
    const float* Bptr = Bm + (size_t)brow * N + bn + bcol;

    for (int k0 = 0; k0 < K; k0 += 8) {
        float4 av = *(const float4*)(Aptr + k0);
        float4 bv = *(const float4*)(Bptr + (size_t)k0 * N);
        __syncthreads();
        As[acol + 0][arow] = av.x;
        As[acol + 1][arow] = av.y;
        As[acol + 2][arow] = av.z;
        As[acol + 3][arow] = av.w;
        *(float4*)&Bs[brow][bcol] = bv;
        __syncthreads();

#pragma unroll
        for (int kk = 0; kk < 8; kk++) {
            float4 a0 = *(const float4*)&As[kk][ty * 8];
            float4 a1 = *(const float4*)&As[kk][ty * 8 + 4];
            float4 b0 = *(const float4*)&Bs[kk][tx * 8];
            float4 b1 = *(const float4*)&Bs[kk][tx * 8 + 4];
            float a[8] = {a0.x, a0.y, a0.z, a0.w, a1.x, a1.y, a1.z, a1.w};
            float b[8] = {b0.x, b0.y, b0.z, b0.w, b1.x, b1.y, b1.z, b1.w};
#pragma unroll
            for (int i = 0; i < 8; i++)
#pragma unroll
                for (int j = 0; j < 8; j++)
                    acc[i][j] = fmaf(a[i], b[j], acc[i][j]);
        }
    }

#pragma unroll
    for (int i = 0; i < 8; i++) {
        const size_t row = (size_t)(bm + ty * 8 + i);
        float* crow = C + row * N + bn + tx * 8;
        float4 c0, c1;
        c0.x = acc[i][0]; c0.y = acc[i][1]; c0.z = acc[i][2]; c0.w = acc[i][3];
        c1.x = acc[i][4]; c1.y = acc[i][5]; c1.z = acc[i][6]; c1.w = acc[i][7];
        if (bias != nullptr) {
            const float* bp = bias + bn + tx * 8;
            c0.x += bp[0]; c0.y += bp[1]; c0.z += bp[2]; c0.w += bp[3];
            c1.x += bp[4]; c1.y += bp[5]; c1.z += bp[6]; c1.w += bp[7];
        }
        *(float4*)(crow)     = c0;
        *(float4*)(crow + 4) = c1;
    }
}

// ---------------------------------------------------------------------------
// Flash attention (fp32, online softmax).
// Grid: (N_Q/64, BATCH*HEADS). Block: 256 threads.
// Each block: 64 query rows x full head (d=64), looping M_KV in 64-key chunks.
// Thread (ty=tid/16, tx=tid%16) owns rows ty*4..+3, cols {tx, tx+16, tx+32, tx+48}.
// ---------------------------------------------------------------------------
#define ASTR 68   // smem row stride (floats): keeps float4 align, 2-way conflicts max

__global__ void __launch_bounds__(256) attn_kernel()
{
    extern __shared__ float sm[];
    float* Qs = sm;                  // [64][ASTR]
    float* Ks = sm + 64 * ASTR;
    float* Vs = sm + 2 * 64 * ASTR;
    float* Ss = sm + 3 * 64 * ASTR;

    const int tid = threadIdx.x;
    const int qt  = blockIdx.x;          // query tile: 64 rows
    const int bh  = blockIdx.y;
    const int b   = bh >> 3;
    const int h   = bh & 7;

    const float* Qp = g_Q + ((size_t)b * N_Q)  * INNER + h * DHEAD;
    const float* Kp = g_K + ((size_t)b * M_KV) * INNER + h * DHEAD;
    const float* Vp = g_V + ((size_t)b * M_KV) * INNER + h * DHEAD;
    float*       Op = g_O + ((size_t)b * N_Q)  * INNER + h * DHEAD;

    // Load Q tile (pre-scaled)
    for (int i = tid; i < 64 * 16; i += 256) {
        const int row = i >> 4;
        const int d4  = (i & 15) << 2;
        float4 v = *(const float4*)(Qp + (size_t)(qt * 64 + row) * INNER + d4);
        v.x *= ATT_SCALE; v.y *= ATT_SCALE; v.z *= ATT_SCALE; v.w *= ATT_SCALE;
        *(float4*)&Qs[row * ASTR + d4] = v;
    }

    const int ty = tid >> 4;
    const int tx = tid & 15;

    float mrow[4], lrow[4], o[4][4];
#pragma unroll
    for (int i = 0; i < 4; i++) {
        mrow[i] = -1e30f;
        lrow[i] = 0.0f;
#pragma unroll
        for (int j = 0; j < 4; j++) o[i][j] = 0.0f;
    }

    for (int j0 = 0; j0 < M_KV; j0 += 64) {
        __syncthreads();  // previous PV done before overwriting K/V/S
        for (int i = tid; i < 64 * 16; i += 256) {
            const int row = i >> 4;
            const int d4  = (i & 15) << 2;
            *(float4*)&Ks[row * ASTR + d4] =
                *(const float4*)(Kp + (size_t)(j0 + row) * INNER + d4);
            *(float4*)&Vs[row * ASTR + d4] =
                *(const float4*)(Vp + (size_t)(j0 + row) * INNER + d4);
        }
        __syncthreads();

        // S = Q * K^T  (4x4 per thread)
        float s[4][4];
#pragma unroll
        for (int i = 0; i < 4; i++)
#pragma unroll
            for (int j = 0; j < 4; j++) s[i][j] = 0.0f;

#pragma unroll 8
        for (int k = 0; k < 64; k++) {
            float a[4], bb[4];
#pragma unroll
            for (int i = 0; i < 4; i++) a[i]  = Qs[(ty * 4 + i) * ASTR + k];
#pragma unroll
            for (int j = 0; j < 4; j++) bb[j] = Ks[(tx + 16 * j) * ASTR + k];
#pragma unroll
            for (int i = 0; i < 4; i++)
#pragma unroll
                for (int j = 0; j < 4; j++)
                    s[i][j] = fmaf(a[i], bb[j], s[i][j]);
        }

        // Online softmax per row (reduce across the 16 tx lanes)
#pragma unroll
        for (int i = 0; i < 4; i++) {
            float mx = fmaxf(fmaxf(s[i][0], s[i][1]), fmaxf(s[i][2], s[i][3]));
#pragma unroll
            for (int off = 1; off < 16; off <<= 1)
                mx = fmaxf(mx, __shfl_xor_sync(0xffffffffu, mx, off));
            const float mnew = fmaxf(mrow[i], mx);
            const float corr = __expf(mrow[i] - mnew);
            mrow[i] = mnew;
            float rs = 0.0f;
#pragma unroll
            for (int j = 0; j < 4; j++) {
                const float p = __expf(s[i][j] - mnew);
                s[i][j] = p;
                rs += p;
            }
#pragma unroll
            for (int off = 1; off < 16; off <<= 1)
                rs += __shfl_xor_sync(0xffffffffu, rs, off);
            lrow[i] = lrow[i] * corr + rs;
#pragma unroll
            for (int j = 0; j < 4; j++) {
                o[i][j] *= corr;
                Ss[(ty * 4 + i) * ASTR + tx + 16 * j] = s[i][j];
            }
        }
        __syncthreads();

        // O += P * V
#pragma unroll 8
        for (int k = 0; k < 64; k++) {
            float p[4], vv[4];
#pragma unroll
            for (int i = 0; i < 4; i++) p[i]  = Ss[(ty * 4 + i) * ASTR + k];
#pragma unroll
            for (int j = 0; j < 4; j++) vv[j] = Vs[k * ASTR + tx + 16 * j];
#pragma unroll
            for (int i = 0; i < 4; i++)
#pragma unroll
                for (int j = 0; j < 4; j++)
                    o[i][j] = fmaf(p[i], vv[j], o[i][j]);
        }
    }

    // Normalize and write out
#pragma unroll
    for (int i = 0; i < 4; i++) {
        const float inv = 1.0f / lrow[i];
        float* orow = Op + (size_t)(qt * 64 + ty * 4 + i) * INNER;
#pragma unroll
        for (int j = 0; j < 4; j++)
            orow[tx + 16 * j] = o[i][j] * inv;
    }
}

// ---------------------------------------------------------------------------
// kernel_launch
// Inputs (metadata order): x, context, Wq, Wk, Wv, Wout, bout   (all fp32)
// Output: [4, 2048, 1024] fp32
// ---------------------------------------------------------------------------
extern "C" void kernel_launch(void* const* d_in, const int* in_sizes, int n_in,
                              void* d_out, int out_size)
{
    const float* x    = (const float*)d_in[0];
    const float* ctx  = (const float*)d_in[1];
    const float* Wq   = (const float*)d_in[2];
    const float* Wk   = (const float*)d_in[3];
    const float* Wv   = (const float*)d_in[4];
    const float* Wout = (const float*)d_in[5];
    const float* bout = (const float*)d_in[6];
    float* out = (float*)d_out;

    float *Qb, *Kb, *Vb, *Ob;
    cudaGetSymbolAddress((void**)&Qb, g_Q);
    cudaGetSymbolAddress((void**)&Kb, g_K);
    cudaGetSymbolAddress((void**)&Vb, g_V);
    cudaGetSymbolAddress((void**)&Ob, g_O);

    const dim3 blk(256);

    // Q = x @ Wq          [8192,1024] x [1024,512]
    sgemm_kernel<<<dim3(INNER / 128, (BATCH * N_Q) / 128), blk>>>(
        x, Wq, nullptr, Qb, BATCH * N_Q, INNER, QD);
    // K = ctx @ Wk        [4096,768] x [768,512]
    sgemm_kernel<<<dim3(INNER / 128, (BATCH * M_KV) / 128), blk>>>(
        ctx, Wk, nullptr, Kb, BATCH * M_KV, INNER, CD);
    // V = ctx @ Wv
    sgemm_kernel<<<dim3(INNER / 128, (BATCH * M_KV) / 128), blk>>>(
        ctx, Wv, nullptr, Vb, BATCH * M_KV, INNER, CD);

    // Attention
    const int smem_bytes = 4 * 64 * ASTR * (int)sizeof(float);  // 69632
    cudaFuncSetAttribute(attn_kernel,
                         cudaFuncAttributeMaxDynamicSharedMemorySize, smem_bytes);
    attn_kernel<<<dim3(N_Q / 64, BATCH * HEADS), blk, smem_bytes>>>();

    // out = O @ Wout + bout   [8192,512] x [512,1024]
    sgemm_kernel<<<dim3(QD / 128, (BATCH * N_Q) / 128), blk>>>(
        Ob, Wout, bout, out, BATCH * N_Q, QD, INNER);
}

// round 3
// speedup vs baseline: 1.4449x; 1.4449x over previous
#include <cuda_runtime.h>
#include <cstdint>
#include <math.h>

// Problem constants
#define BATCH   4
#define N_Q     2048
#define M_KV    1024
#define QD      1024
#define CD      768
#define HEADS   8
#define DHEAD   64
#define INNER   (HEADS * DHEAD)   // 512
#define ATT_SCALE 0.125f

// Device-global scratch (allocation-free per harness rules)
__device__ float g_Q[(size_t)BATCH * N_Q * INNER];
__device__ float g_K[(size_t)BATCH * M_KV * INNER];
__device__ float g_V[(size_t)BATCH * M_KV * INNER];
__device__ float g_O[(size_t)BATCH * N_Q * INNER];

__device__ __forceinline__ float to_tf32(float x) {
    float r;
    asm("cvt.rna.tf32.f32 %0, %1;" : "=f"(r) : "f"(x));
    return r;
}

__device__ __forceinline__ void mma1688(float c[4], const uint32_t a[4],
                                        const uint32_t b[2]) {
    asm volatile(
        "mma.sync.aligned.m16n8k8.row.col.f32.tf32.tf32.f32 "
        "{%0,%1,%2,%3}, {%4,%5,%6,%7}, {%8,%9}, {%0,%1,%2,%3};"
        : "+f"(c[0]), "+f"(c[1]), "+f"(c[2]), "+f"(c[3])
        : "r"(a[0]), "r"(a[1]), "r"(a[2]), "r"(a[3]), "r"(b[0]), "r"(b[1]));
}

// ---------------------------------------------------------------------------
// TF32 mma.sync GEMM: C[M,N] = A[M,K] @ B[K,N] (+bias)
// 128x128 tile, BK=32, 256 threads (8 warps as 2x4), warp tile 64x32.
// SMEM: As[128][36] (row-major, pad 4), Bs[32][136] (pad 8), double buffered.
// Requires M%128==0, N%128==0, K%64==0.
// ---------------------------------------------------------------------------
#define BM 128
#define BN 128
#define BK 32
#define ASTRIDE 36
#define BSTRIDE 136
#define AS_FLOATS (BM * ASTRIDE)          // 4608
#define BS_FLOATS (BK * BSTRIDE)          // 4352
#define GEMM_SMEM ((2 * (AS_FLOATS + BS_FLOATS)) * 4)  // 71680 B

__global__ void __launch_bounds__(256) mma_gemm(
    const float* __restrict__ A, const float* __restrict__ B,
    const float* __restrict__ bias, float* __restrict__ C,
    int M, int N, int K)
{
    extern __shared__ float sh[];
    float* As[2] = { sh, sh + AS_FLOATS };
    float* Bs[2] = { sh + 2 * AS_FLOATS, sh + 2 * AS_FLOATS + BS_FLOATS };

    const int tid = threadIdx.x;
    const int wid = tid >> 5;
    const int lane = tid & 31;
    const int g  = lane >> 2;     // group id 0..7
    const int kq = lane & 3;      // quad id 0..3
    const int warp_m = wid >> 2;  // 0..1 -> 64 rows each
    const int warp_n = wid & 3;   // 0..3 -> 32 cols each
    const int bm = blockIdx.y * BM;
    const int bn = blockIdx.x * BN;

    // staging-reg load mappings
    const int a_row[4] = { (tid + 0) >> 3, (tid + 256) >> 3,
                           (tid + 512) >> 3, (tid + 768) >> 3 };
    const int a_seg = tid & 7;              // same for all t (tid + t*256, 256%8==0)
    const int b_k[4] = { (tid + 0) >> 5, (tid + 256) >> 5,
                         (tid + 512) >> 5, (tid + 768) >> 5 };
    const int b_seg = tid & 31;

    float4 aST[4], bST[4];
    float c[4][4][4];
#pragma unroll
    for (int mi = 0; mi < 4; mi++)
#pragma unroll
        for (int ni = 0; ni < 4; ni++)
#pragma unroll
            for (int t = 0; t < 4; t++) c[mi][ni][t] = 0.0f;

    const int NC = K / BK;

    // load chunk 0
#pragma unroll
    for (int t = 0; t < 4; t++) {
        aST[t] = *(const float4*)(A + (size_t)(bm + a_row[t]) * K + a_seg * 4);
        bST[t] = *(const float4*)(B + (size_t)b_k[t] * N + bn + b_seg * 4);
    }
    // store chunk 0 to buffer 0 (with RNA tf32 rounding)
#pragma unroll
    for (int t = 0; t < 4; t++) {
        float4 av = aST[t];
        av.x = to_tf32(av.x); av.y = to_tf32(av.y);
        av.z = to_tf32(av.z); av.w = to_tf32(av.w);
        *(float4*)&As[0][a_row[t] * ASTRIDE + a_seg * 4] = av;
        float4 bv = bST[t];
        bv.x = to_tf32(bv.x); bv.y = to_tf32(bv.y);
        bv.z = to_tf32(bv.z); bv.w = to_tf32(bv.w);
        *(float4*)&Bs[0][b_k[t] * BSTRIDE + b_seg * 4] = bv;
    }

    for (int kc = 0; kc < NC; kc++) {
        const int p = kc & 1;
        __syncthreads();

        // prefetch next chunk into regs (in flight during mma)
        if (kc + 1 < NC) {
            const int k0 = (kc + 1) * BK;
#pragma unroll
            for (int t = 0; t < 4; t++) {
                aST[t] = *(const float4*)(A + (size_t)(bm + a_row[t]) * K + k0 + a_seg * 4);
                bST[t] = *(const float4*)(B + (size_t)(k0 + b_k[t]) * N + bn + b_seg * 4);
            }
        }

        // compute chunk kc from buffer p
        const float* Ap = As[p];
        const float* Bp = Bs[p];
#pragma unroll
        for (int ks = 0; ks < 4; ks++) {
            const int kk = ks * 8;
            uint32_t af[4][4], bf[4][2];
#pragma unroll
            for (int mi = 0; mi < 4; mi++) {
                const int base = (warp_m * 64 + mi * 16 + g) * ASTRIDE + kk + kq;
                af[mi][0] = __float_as_uint(Ap[base]);
                af[mi][1] = __float_as_uint(Ap[base + 8 * ASTRIDE]);
                af[mi][2] = __float_as_uint(Ap[base + 4]);
                af[mi][3] = __float_as_uint(Ap[base + 8 * ASTRIDE + 4]);
            }
#pragma unroll
            for (int ni = 0; ni < 4; ni++) {
                const int colb = warp_n * 32 + ni * 8 + g;
                bf[ni][0] = __float_as_uint(Bp[(kk + kq) * BSTRIDE + colb]);
                bf[ni][1] = __float_as_uint(Bp[(kk + kq + 4) * BSTRIDE + colb]);
            }
#pragma unroll
            for (int mi = 0; mi < 4; mi++)
#pragma unroll
                for (int ni = 0; ni < 4; ni++)
                    mma1688(c[mi][ni], af[mi], bf[ni]);
        }

        // store prefetched chunk into the other buffer
        if (kc + 1 < NC) {
            float* An = As[p ^ 1];
            float* Bn = Bs[p ^ 1];
#pragma unroll
            for (int t = 0; t < 4; t++) {
                float4 av = aST[t];
                av.x = to_tf32(av.x); av.y = to_tf32(av.y);
                av.z = to_tf32(av.z); av.w = to_tf32(av.w);
                *(float4*)&An[a_row[t] * ASTRIDE + a_seg * 4] = av;
                float4 bv = bST[t];
                bv.x = to_tf32(bv.x); bv.y = to_tf32(bv.y);
                bv.z = to_tf32(bv.z); bv.w = to_tf32(bv.w);
                *(float4*)&Bn[b_k[t] * BSTRIDE + b_seg * 4] = bv;
            }
        }
    }

    // epilogue: c-frag (mi,ni): rows g,g+8 cols 2*kq,2*kq+1
#pragma unroll
    for (int mi = 0; mi < 4; mi++) {
        const int row0 = bm + warp_m * 64 + mi * 16 + g;
#pragma unroll
        for (int ni = 0; ni < 4; ni++) {
            const int col = bn + warp_n * 32 + ni * 8 + 2 * kq;
            float2 v0 = make_float2(c[mi][ni][0], c[mi][ni][1]);
            float2 v1 = make_float2(c[mi][ni][2], c[mi][ni][3]);
            if (bias != nullptr) {
                const float2 bv = *(const float2*)(bias + col);
                v0.x += bv.x; v0.y += bv.y;
                v1.x += bv.x; v1.y += bv.y;
            }
            *(float2*)(C + (size_t)row0 * N + col)       = v0;
            *(float2*)(C + (size_t)(row0 + 8) * N + col) = v1;
        }
    }
}

// ---------------------------------------------------------------------------
// Flash attention (fp32, online softmax) — unchanged (R1 proven).
// ---------------------------------------------------------------------------
#define ASTR 68

__global__ void __launch_bounds__(256) attn_kernel()
{
    extern __shared__ float sm[];
    float* Qs = sm;
    float* Ks = sm + 64 * ASTR;
    float* Vs = sm + 2 * 64 * ASTR;
    float* Ss = sm + 3 * 64 * ASTR;

    const int tid = threadIdx.x;
    const int qt  = blockIdx.x;
    const int bh  = blockIdx.y;
    const int b   = bh >> 3;
    const int h   = bh & 7;

    const float* Qp = g_Q + ((size_t)b * N_Q)  * INNER + h * DHEAD;
    const float* Kp = g_K + ((size_t)b * M_KV) * INNER + h * DHEAD;
    const float* Vp = g_V + ((size_t)b * M_KV) * INNER + h * DHEAD;
    float*       Op = g_O + ((size_t)b * N_Q)  * INNER + h * DHEAD;

    for (int i = tid; i < 64 * 16; i += 256) {
        const int row = i >> 4;
        const int d4  = (i & 15) << 2;
        float4 v = *(const float4*)(Qp + (size_t)(qt * 64 + row) * INNER + d4);
        v.x *= ATT_SCALE; v.y *= ATT_SCALE; v.z *= ATT_SCALE; v.w *= ATT_SCALE;
        *(float4*)&Qs[row * ASTR + d4] = v;
    }

    const int ty = tid >> 4;
    const int tx = tid & 15;

    float mrow[4], lrow[4], o[4][4];
#pragma unroll
    for (int i = 0; i < 4; i++) {
        mrow[i] = -1e30f;
        lrow[i] = 0.0f;
#pragma unroll
        for (int j = 0; j < 4; j++) o[i][j] = 0.0f;
    }

    for (int j0 = 0; j0 < M_KV; j0 += 64) {
        __syncthreads();
        for (int i = tid; i < 64 * 16; i += 256) {
            const int row = i >> 4;
            const int d4  = (i & 15) << 2;
            *(float4*)&Ks[row * ASTR + d4] =
                *(const float4*)(Kp + (size_t)(j0 + row) * INNER + d4);
            *(float4*)&Vs[row * ASTR + d4] =
                *(const float4*)(Vp + (size_t)(j0 + row) * INNER + d4);
        }
        __syncthreads();

        float s[4][4];
#pragma unroll
        for (int i = 0; i < 4; i++)
#pragma unroll
            for (int j = 0; j < 4; j++) s[i][j] = 0.0f;

#pragma unroll 8
        for (int k = 0; k < 64; k++) {
            float a[4], bb[4];
#pragma unroll
            for (int i = 0; i < 4; i++) a[i]  = Qs[(ty * 4 + i) * ASTR + k];
#pragma unroll
            for (int j = 0; j < 4; j++) bb[j] = Ks[(tx + 16 * j) * ASTR + k];
#pragma unroll
            for (int i = 0; i < 4; i++)
#pragma unroll
                for (int j = 0; j < 4; j++)
                    s[i][j] = fmaf(a[i], bb[j], s[i][j]);
        }

#pragma unroll
        for (int i = 0; i < 4; i++) {
            float mx = fmaxf(fmaxf(s[i][0], s[i][1]), fmaxf(s[i][2], s[i][3]));
#pragma unroll
            for (int off = 1; off < 16; off <<= 1)
                mx = fmaxf(mx, __shfl_xor_sync(0xffffffffu, mx, off));
            const float mnew = fmaxf(mrow[i], mx);
            const float corr = __expf(mrow[i] - mnew);
            mrow[i] = mnew;
            float rs = 0.0f;
#pragma unroll
            for (int j = 0; j < 4; j++) {
                const float p = __expf(s[i][j] - mnew);
                s[i][j] = p;
                rs += p;
            }
#pragma unroll
            for (int off = 1; off < 16; off <<= 1)
                rs += __shfl_xor_sync(0xffffffffu, rs, off);
            lrow[i] = lrow[i] * corr + rs;
#pragma unroll
            for (int j = 0; j < 4; j++) {
                o[i][j] *= corr;
                Ss[(ty * 4 + i) * ASTR + tx + 16 * j] = s[i][j];
            }
        }
        __syncthreads();

#pragma unroll 8
        for (int k = 0; k < 64; k++) {
            float p[4], vv[4];
#pragma unroll
            for (int i = 0; i < 4; i++) p[i]  = Ss[(ty * 4 + i) * ASTR + k];
#pragma unroll
            for (int j = 0; j < 4; j++) vv[j] = Vs[k * ASTR + tx + 16 * j];
#pragma unroll
            for (int i = 0; i < 4; i++)
#pragma unroll
                for (int j = 0; j < 4; j++)
                    o[i][j] = fmaf(p[i], vv[j], o[i][j]);
        }
    }

#pragma unroll
    for (int i = 0; i < 4; i++) {
        const float inv = 1.0f / lrow[i];
        float* orow = Op + (size_t)(qt * 64 + ty * 4 + i) * INNER;
#pragma unroll
        for (int j = 0; j < 4; j++)
            orow[tx + 16 * j] = o[i][j] * inv;
    }
}

// ---------------------------------------------------------------------------
// kernel_launch
// ---------------------------------------------------------------------------
extern "C" void kernel_launch(void* const* d_in, const int* in_sizes, int n_in,
                              void* d_out, int out_size)
{
    const float* x    = (const float*)d_in[0];
    const float* ctx  = (const float*)d_in[1];
    const float* Wq   = (const float*)d_in[2];
    const float* Wk   = (const float*)d_in[3];
    const float* Wv   = (const float*)d_in[4];
    const float* Wout = (const float*)d_in[5];
    const float* bout = (const float*)d_in[6];
    float* out = (float*)d_out;

    float *Qb, *Kb, *Vb, *Ob;
    cudaGetSymbolAddress((void**)&Qb, g_Q);
    cudaGetSymbolAddress((void**)&Kb, g_K);
    cudaGetSymbolAddress((void**)&Vb, g_V);
    cudaGetSymbolAddress((void**)&Ob, g_O);

    cudaFuncSetAttribute(mma_gemm,
                         cudaFuncAttributeMaxDynamicSharedMemorySize, GEMM_SMEM);

    const dim3 blk(256);

    // Q = x @ Wq
    mma_gemm<<<dim3(INNER / BN, (BATCH * N_Q) / BM), blk, GEMM_SMEM>>>(
        x, Wq, nullptr, Qb, BATCH * N_Q, INNER, QD);
    // K = ctx @ Wk
    mma_gemm<<<dim3(INNER / BN, (BATCH * M_KV) / BM), blk, GEMM_SMEM>>>(
        ctx, Wk, nullptr, Kb, BATCH * M_KV, INNER, CD);
    // V = ctx @ Wv
    mma_gemm<<<dim3(INNER / BN, (BATCH * M_KV) / BM), blk, GEMM_SMEM>>>(
        ctx, Wv, nullptr, Vb, BATCH * M_KV, INNER, CD);

    // Attention
    const int smem_bytes = 4 * 64 * ASTR * (int)sizeof(float);
    cudaFuncSetAttribute(attn_kernel,
                         cudaFuncAttributeMaxDynamicSharedMemorySize, smem_bytes);
    attn_kernel<<<dim3(N_Q / 64, BATCH * HEADS), blk, smem_bytes>>>();

    // out = O @ Wout + bout
    mma_gemm<<<dim3(QD / BN, (BATCH * N_Q) / BM), blk, GEMM_SMEM>>>(
        Ob, Wout, bout, out, BATCH * N_Q, QD, INNER);
}

// round 4
// speedup vs baseline: 2.9440x; 2.0375x over previous
#include <cuda_runtime.h>
#include <cuda_fp16.h>
#include <cstdint>
#include <math.h>

// Problem constants
#define BATCH   4
#define N_Q     2048
#define M_KV    1024
#define QD      1024
#define CD      768
#define HEADS   8
#define DHEAD   64
#define INNER   (HEADS * DHEAD)   // 512
#define ATT_SCALE 0.125f

// Device-global scratch
__device__ __half g_Qh[(size_t)BATCH * N_Q * INNER];
__device__ __half g_Kh[(size_t)BATCH * M_KV * INNER];
__device__ __half g_Vh[(size_t)BATCH * M_KV * INNER];
__device__ float  g_O [(size_t)BATCH * N_Q * INNER];

__device__ __forceinline__ float to_tf32(float x) {
    float r;
    asm("cvt.rna.tf32.f32 %0, %1;" : "=f"(r) : "f"(x));
    return r;
}

__device__ __forceinline__ uint32_t smem_u32(const void* p) {
    uint32_t a;
    asm("{ .reg .u64 t; cvta.to.shared.u64 t, %1; cvt.u32.u64 %0, t; }"
        : "=r"(a) : "l"(p));
    return a;
}

__device__ __forceinline__ uint32_t pack_f16x2(float lo, float hi) {
    uint32_t r;
    asm("cvt.rn.f16x2.f32 %0, %1, %2;" : "=r"(r) : "f"(hi), "f"(lo));
    return r;
}

__device__ __forceinline__ void mma1688(float c[4], const uint32_t a[4],
                                        const uint32_t b[2]) {
    asm volatile(
        "mma.sync.aligned.m16n8k8.row.col.f32.tf32.tf32.f32 "
        "{%0,%1,%2,%3}, {%4,%5,%6,%7}, {%8,%9}, {%0,%1,%2,%3};"
        : "+f"(c[0]), "+f"(c[1]), "+f"(c[2]), "+f"(c[3])
        : "r"(a[0]), "r"(a[1]), "r"(a[2]), "r"(a[3]), "r"(b[0]), "r"(b[1]));
}

__device__ __forceinline__ void mma16816h(float c[4], const uint32_t a[4],
                                          const uint32_t b0, const uint32_t b1) {
    asm volatile(
        "mma.sync.aligned.m16n8k16.row.col.f32.f16.f16.f32 "
        "{%0,%1,%2,%3}, {%4,%5,%6,%7}, {%8,%9}, {%0,%1,%2,%3};"
        : "+f"(c[0]), "+f"(c[1]), "+f"(c[2]), "+f"(c[3])
        : "r"(a[0]), "r"(a[1]), "r"(a[2]), "r"(a[3]), "r"(b0), "r"(b1));
}

__device__ __forceinline__ void ldmx4(uint32_t r[4], uint32_t addr) {
    asm volatile("ldmatrix.sync.aligned.m8n8.x4.shared.b16 {%0,%1,%2,%3}, [%4];"
                 : "=r"(r[0]), "=r"(r[1]), "=r"(r[2]), "=r"(r[3]) : "r"(addr));
}
__device__ __forceinline__ void ldmx4t(uint32_t r[4], uint32_t addr) {
    asm volatile("ldmatrix.sync.aligned.m8n8.x4.trans.shared.b16 {%0,%1,%2,%3}, [%4];"
                 : "=r"(r[0]), "=r"(r[1]), "=r"(r[2]), "=r"(r[3]) : "r"(addr));
}

// ---------------------------------------------------------------------------
// TF32 mma.sync GEMM (R3-proven). OUT16: write __half C, else float C (+bias).
// ---------------------------------------------------------------------------
#define BM 128
#define BN 128
#define BK 32
#define ASTRIDE 36
#define BSTRIDE 136
#define AS_FLOATS (BM * ASTRIDE)
#define BS_FLOATS (BK * BSTRIDE)
#define GEMM_SMEM ((2 * (AS_FLOATS + BS_FLOATS)) * 4)

template <int OUT16>
__global__ void __launch_bounds__(256) mma_gemm(
    const float* __restrict__ A, const float* __restrict__ B,
    const float* __restrict__ bias, void* __restrict__ Cv,
    int M, int N, int K)
{
    extern __shared__ float sh[];
    float* As[2] = { sh, sh + AS_FLOATS };
    float* Bs[2] = { sh + 2 * AS_FLOATS, sh + 2 * AS_FLOATS + BS_FLOATS };

    const int tid = threadIdx.x;
    const int wid = tid >> 5;
    const int lane = tid & 31;
    const int g  = lane >> 2;
    const int kq = lane & 3;
    const int warp_m = wid >> 2;
    const int warp_n = wid & 3;
    const int bm = blockIdx.y * BM;
    const int bn = blockIdx.x * BN;

    const int a_row[4] = { (tid + 0) >> 3, (tid + 256) >> 3,
                           (tid + 512) >> 3, (tid + 768) >> 3 };
    const int a_seg = tid & 7;
    const int b_k[4] = { (tid + 0) >> 5, (tid + 256) >> 5,
                         (tid + 512) >> 5, (tid + 768) >> 5 };
    const int b_seg = tid & 31;

    float4 aST[4], bST[4];
    float c[4][4][4];
#pragma unroll
    for (int mi = 0; mi < 4; mi++)
#pragma unroll
        for (int ni = 0; ni < 4; ni++)
#pragma unroll
            for (int t = 0; t < 4; t++) c[mi][ni][t] = 0.0f;

    const int NC = K / BK;

#pragma unroll
    for (int t = 0; t < 4; t++) {
        aST[t] = *(const float4*)(A + (size_t)(bm + a_row[t]) * K + a_seg * 4);
        bST[t] = *(const float4*)(B + (size_t)b_k[t] * N + bn + b_seg * 4);
    }
#pragma unroll
    for (int t = 0; t < 4; t++) {
        float4 av = aST[t];
        av.x = to_tf32(av.x); av.y = to_tf32(av.y);
        av.z = to_tf32(av.z); av.w = to_tf32(av.w);
        *(float4*)&As[0][a_row[t] * ASTRIDE + a_seg * 4] = av;
        float4 bv = bST[t];
        bv.x = to_tf32(bv.x); bv.y = to_tf32(bv.y);
        bv.z = to_tf32(bv.z); bv.w = to_tf32(bv.w);
        *(float4*)&Bs[0][b_k[t] * BSTRIDE + b_seg * 4] = bv;
    }

    for (int kc = 0; kc < NC; kc++) {
        const int p = kc & 1;
        __syncthreads();

        if (kc + 1 < NC) {
            const int k0 = (kc + 1) * BK;
#pragma unroll
            for (int t = 0; t < 4; t++) {
                aST[t] = *(const float4*)(A + (size_t)(bm + a_row[t]) * K + k0 + a_seg * 4);
                bST[t] = *(const float4*)(B + (size_t)(k0 + b_k[t]) * N + bn + b_seg * 4);
            }
        }

        const float* Ap = As[p];
        const float* Bp = Bs[p];
#pragma unroll
        for (int ks = 0; ks < 4; ks++) {
            const int kk = ks * 8;
            uint32_t af[4][4], bf[4][2];
#pragma unroll
            for (int mi = 0; mi < 4; mi++) {
                const int base = (warp_m * 64 + mi * 16 + g) * ASTRIDE + kk + kq;
                af[mi][0] = __float_as_uint(Ap[base]);
                af[mi][1] = __float_as_uint(Ap[base + 8 * ASTRIDE]);
                af[mi][2] = __float_as_uint(Ap[base + 4]);
                af[mi][3] = __float_as_uint(Ap[base + 8 * ASTRIDE + 4]);
            }
#pragma unroll
            for (int ni = 0; ni < 4; ni++) {
                const int colb = warp_n * 32 + ni * 8 + g;
                bf[ni][0] = __float_as_uint(Bp[(kk + kq) * BSTRIDE + colb]);
                bf[ni][1] = __float_as_uint(Bp[(kk + kq + 4) * BSTRIDE + colb]);
            }
#pragma unroll
            for (int mi = 0; mi < 4; mi++)
#pragma unroll
                for (int ni = 0; ni < 4; ni++)
                    mma1688(c[mi][ni], af[mi], bf[ni]);
        }

        if (kc + 1 < NC) {
            float* An = As[p ^ 1];
            float* Bn = Bs[p ^ 1];
#pragma unroll
            for (int t = 0; t < 4; t++) {
                float4 av = aST[t];
                av.x = to_tf32(av.x); av.y = to_tf32(av.y);
                av.z = to_tf32(av.z); av.w = to_tf32(av.w);
                *(float4*)&An[a_row[t] * ASTRIDE + a_seg * 4] = av;
                float4 bv = bST[t];
                bv.x = to_tf32(bv.x); bv.y = to_tf32(bv.y);
                bv.z = to_tf32(bv.z); bv.w = to_tf32(bv.w);
                *(float4*)&Bn[b_k[t] * BSTRIDE + b_seg * 4] = bv;
            }
        }
    }

#pragma unroll
    for (int mi = 0; mi < 4; mi++) {
        const int row0 = bm + warp_m * 64 + mi * 16 + g;
#pragma unroll
        for (int ni = 0; ni < 4; ni++) {
            const int col = bn + warp_n * 32 + ni * 8 + 2 * kq;
            if (OUT16) {
                __half* Ch = (__half*)Cv;
                *(uint32_t*)(Ch + (size_t)row0 * N + col) =
                    pack_f16x2(c[mi][ni][0], c[mi][ni][1]);
                *(uint32_t*)(Ch + (size_t)(row0 + 8) * N + col) =
                    pack_f16x2(c[mi][ni][2], c[mi][ni][3]);
            } else {
                float* C = (float*)Cv;
                float2 v0 = make_float2(c[mi][ni][0], c[mi][ni][1]);
                float2 v1 = make_float2(c[mi][ni][2], c[mi][ni][3]);
                if (bias != nullptr) {
                    const float2 bv = *(const float2*)(bias + col);
                    v0.x += bv.x; v0.y += bv.y;
                    v1.x += bv.x; v1.y += bv.y;
                }
                *(float2*)(C + (size_t)row0 * N + col)       = v0;
                *(float2*)(C + (size_t)(row0 + 8) * N + col) = v1;
            }
        }
    }
}

// ---------------------------------------------------------------------------
// fp16 tensor-core flash attention.
// Grid: (N_Q/128, BATCH*HEADS), 256 threads (8 warps x 16 q-rows).
// Q tile 128x64 resident in registers (a-frags), KV chunks of 64.
// S fragments -> softmax in registers -> P a-frags via cvt (no smem).
// ---------------------------------------------------------------------------
#define QSTR 88   // halves; conflict-free for ldmatrix (stride 44 words)
#define ATTN_SMEM ((128 * QSTR + 2 * 64 * QSTR) * 2)   // 45056 B

__global__ void __launch_bounds__(256) attn16_kernel()
{
    extern __shared__ __half sha[];
    __half* Qs = sha;                     // [128][QSTR]
    __half* Ks = sha + 128 * QSTR;        // [64][QSTR]
    __half* Vs = sha + 192 * QSTR;        // [64][QSTR]

    const int tid  = threadIdx.x;
    const int wid  = tid >> 5;
    const int lane = tid & 31;
    const int qt   = blockIdx.x;
    const int bh   = blockIdx.y;
    const int b    = bh >> 3;
    const int h    = bh & 7;

    const __half* Qp = g_Qh + ((size_t)b * N_Q)  * INNER + h * DHEAD;
    const __half* Kp = g_Kh + ((size_t)b * M_KV) * INNER + h * DHEAD;
    const __half* Vp = g_Vh + ((size_t)b * M_KV) * INNER + h * DHEAD;
    float*        Op = g_O  + ((size_t)b * N_Q)  * INNER + h * DHEAD;

    // Load Q tile -> smem (128 rows x 64 halves; 16B per thread-iter)
    {
        const int row = tid >> 1;
        const int seg = (tid & 1) * 4;    // two uint4 segs of 8 halves... seg in [0,4)
#pragma unroll
        for (int t = 0; t < 2; t++) {
            const int s = seg + t * 2;    // uint4 index 0..3 within row halves 0..63? (8h each)
            // use flat mapping instead:
            (void)s;
        }
    }
    // (flat mapping, 4 iters of 256 threads x 16B)
    for (int i = tid; i < 128 * 8; i += 256) {
        const int row = i >> 3;
        const int seg = i & 7;
        *(uint4*)&Qs[row * QSTR + seg * 8] =
            *(const uint4*)(Qp + (size_t)(qt * 128 + row) * INNER + seg * 8);
    }
    __syncthreads();

    // Q a-frags (per warp: 16 rows x 64 d = 4 k-steps)
    const uint32_t qbase = smem_u32(Qs);
    const uint32_t kbase = smem_u32(Ks);
    const uint32_t vbase = smem_u32(Vs);
    uint32_t qa[4][4];
    {
        const int r0 = wid * 16;
#pragma unroll
        for (int t = 0; t < 4; t++) {
            const uint32_t addr = qbase +
                (uint32_t)(((r0 + (lane & 15)) * QSTR + t * 16 + ((lane >> 4) << 3)) * 2);
            ldmx4(qa[t], addr);
        }
    }

    float o[8][4];
#pragma unroll
    for (int j = 0; j < 8; j++)
#pragma unroll
        for (int t = 0; t < 4; t++) o[j][t] = 0.0f;
    float mrow[2] = { -1e30f, -1e30f };
    float lrow[2] = { 0.0f, 0.0f };

    // prefetch chunk 0 (K,V: 64x64 halves each; 2 uint4 per thread per tile)
    const int ld_row[2] = { tid >> 3, (tid + 256) >> 3 };
    const int ld_seg = tid & 7;
    uint4 kpf[2], vpf[2];
#pragma unroll
    for (int t = 0; t < 2; t++) {
        kpf[t] = *(const uint4*)(Kp + (size_t)ld_row[t] * INNER + ld_seg * 8);
        vpf[t] = *(const uint4*)(Vp + (size_t)ld_row[t] * INNER + ld_seg * 8);
    }

    const int NCH = M_KV / 64;
    for (int c = 0; c < NCH; c++) {
        // store prefetched chunk
#pragma unroll
        for (int t = 0; t < 2; t++) {
            *(uint4*)&Ks[ld_row[t] * QSTR + ld_seg * 8] = kpf[t];
            *(uint4*)&Vs[ld_row[t] * QSTR + ld_seg * 8] = vpf[t];
        }
        __syncthreads();

        // prefetch next chunk
        if (c + 1 < NCH) {
            const size_t base = (size_t)(c + 1) * 64;
#pragma unroll
            for (int t = 0; t < 2; t++) {
                kpf[t] = *(const uint4*)(Kp + (base + ld_row[t]) * INNER + ld_seg * 8);
                vpf[t] = *(const uint4*)(Vp + (base + ld_row[t]) * INNER + ld_seg * 8);
            }
        }

        // S = Q @ K^T  (128x64 per CTA; per warp 16x64)
        float sc[8][4];
#pragma unroll
        for (int n = 0; n < 8; n++)
#pragma unroll
            for (int t = 0; t < 4; t++) sc[n][t] = 0.0f;

#pragma unroll
        for (int np = 0; np < 4; np++) {
#pragma unroll
            for (int t = 0; t < 4; t++) {
                uint32_t kb[4];
                const uint32_t addr = kbase + (uint32_t)((
                    (16 * np + (lane & 7) + 8 * (lane >> 4)) * QSTR +
                    16 * t + 8 * ((lane >> 3) & 1)) * 2);
                ldmx4(kb, addr);
                mma16816h(sc[2 * np],     qa[t], kb[0], kb[1]);
                mma16816h(sc[2 * np + 1], qa[t], kb[2], kb[3]);
            }
        }

        // online softmax (rows g and g+8, scale folded into exp)
        float mx0 = -1e30f, mx1 = -1e30f;
#pragma unroll
        for (int n = 0; n < 8; n++) {
            mx0 = fmaxf(mx0, fmaxf(sc[n][0], sc[n][1]));
            mx1 = fmaxf(mx1, fmaxf(sc[n][2], sc[n][3]));
        }
        mx0 = fmaxf(mx0, __shfl_xor_sync(0xffffffffu, mx0, 1));
        mx0 = fmaxf(mx0, __shfl_xor_sync(0xffffffffu, mx0, 2));
        mx1 = fmaxf(mx1, __shfl_xor_sync(0xffffffffu, mx1, 1));
        mx1 = fmaxf(mx1, __shfl_xor_sync(0xffffffffu, mx1, 2));

        const float mn0 = fmaxf(mrow[0], mx0);
        const float mn1 = fmaxf(mrow[1], mx1);
        const float cr0 = __expf(ATT_SCALE * (mrow[0] - mn0));
        const float cr1 = __expf(ATT_SCALE * (mrow[1] - mn1));
        mrow[0] = mn0; mrow[1] = mn1;

        float rs0 = 0.0f, rs1 = 0.0f;
#pragma unroll
        for (int n = 0; n < 8; n++) {
            sc[n][0] = __expf(ATT_SCALE * (sc[n][0] - mn0));
            sc[n][1] = __expf(ATT_SCALE * (sc[n][1] - mn0));
            sc[n][2] = __expf(ATT_SCALE * (sc[n][2] - mn1));
            sc[n][3] = __expf(ATT_SCALE * (sc[n][3] - mn1));
            rs0 += sc[n][0] + sc[n][1];
            rs1 += sc[n][2] + sc[n][3];
        }
        rs0 += __shfl_xor_sync(0xffffffffu, rs0, 1);
        rs0 += __shfl_xor_sync(0xffffffffu, rs0, 2);
        rs1 += __shfl_xor_sync(0xffffffffu, rs1, 1);
        rs1 += __shfl_xor_sync(0xffffffffu, rs1, 2);
        lrow[0] = lrow[0] * cr0 + rs0;
        lrow[1] = lrow[1] * cr1 + rs1;

#pragma unroll
        for (int j = 0; j < 8; j++) {
            o[j][0] *= cr0; o[j][1] *= cr0;
            o[j][2] *= cr1; o[j][3] *= cr1;
        }

        // P a-frags
        uint32_t pa[4][4];
#pragma unroll
        for (int t = 0; t < 4; t++) {
            pa[t][0] = pack_f16x2(sc[2 * t][0],     sc[2 * t][1]);
            pa[t][1] = pack_f16x2(sc[2 * t][2],     sc[2 * t][3]);
            pa[t][2] = pack_f16x2(sc[2 * t + 1][0], sc[2 * t + 1][1]);
            pa[t][3] = pack_f16x2(sc[2 * t + 1][2], sc[2 * t + 1][3]);
        }

        // O += P @ V
#pragma unroll
        for (int t = 0; t < 4; t++) {
#pragma unroll
            for (int jp = 0; jp < 4; jp++) {
                uint32_t vb[4];
                const uint32_t addr = vbase + (uint32_t)((
                    (16 * t + (lane & 15)) * QSTR +
                    16 * jp + ((lane >> 4) << 3)) * 2);
                ldmx4t(vb, addr);
                mma16816h(o[2 * jp],     pa[t], vb[0], vb[1]);
                mma16816h(o[2 * jp + 1], pa[t], vb[2], vb[3]);
            }
        }
        __syncthreads();
    }

    // normalize + write
    const float inv0 = 1.0f / lrow[0];
    const float inv1 = 1.0f / lrow[1];
    const int g  = lane >> 2;
    const int kq = lane & 3;
    const int row0 = qt * 128 + wid * 16 + g;
#pragma unroll
    for (int j = 0; j < 8; j++) {
        const int col = j * 8 + 2 * kq;
        *(float2*)(Op + (size_t)row0 * INNER + col) =
            make_float2(o[j][0] * inv0, o[j][1] * inv0);
        *(float2*)(Op + (size_t)(row0 + 8) * INNER + col) =
            make_float2(o[j][2] * inv1, o[j][3] * inv1);
    }
}

// ---------------------------------------------------------------------------
// kernel_launch
// ---------------------------------------------------------------------------
extern "C" void kernel_launch(void* const* d_in, const int* in_sizes, int n_in,
                              void* d_out, int out_size)
{
    const float* x    = (const float*)d_in[0];
    const float* ctx  = (const float*)d_in[1];
    const float* Wq   = (const float*)d_in[2];
    const float* Wk   = (const float*)d_in[3];
    const float* Wv   = (const float*)d_in[4];
    const float* Wout = (const float*)d_in[5];
    const float* bout = (const float*)d_in[6];
    float* out = (float*)d_out;

    __half *Qb, *Kb, *Vb;
    float *Ob;
    cudaGetSymbolAddress((void**)&Qb, g_Qh);
    cudaGetSymbolAddress((void**)&Kb, g_Kh);
    cudaGetSymbolAddress((void**)&Vb, g_Vh);
    cudaGetSymbolAddress((void**)&Ob, g_O);

    cudaFuncSetAttribute(mma_gemm<0>,
                         cudaFuncAttributeMaxDynamicSharedMemorySize, GEMM_SMEM);
    cudaFuncSetAttribute(mma_gemm<1>,
                         cudaFuncAttributeMaxDynamicSharedMemorySize, GEMM_SMEM);
    cudaFuncSetAttribute(attn16_kernel,
                         cudaFuncAttributeMaxDynamicSharedMemorySize, ATTN_SMEM);

    const dim3 blk(256);

    // Projections -> fp16
    mma_gemm<1><<<dim3(INNER / BN, (BATCH * N_Q) / BM), blk, GEMM_SMEM>>>(
        x, Wq, nullptr, Qb, BATCH * N_Q, INNER, QD);
    mma_gemm<1><<<dim3(INNER / BN, (BATCH * M_KV) / BM), blk, GEMM_SMEM>>>(
        ctx, Wk, nullptr, Kb, BATCH * M_KV, INNER, CD);
    mma_gemm<1><<<dim3(INNER / BN, (BATCH * M_KV) / BM), blk, GEMM_SMEM>>>(
        ctx, Wv, nullptr, Vb, BATCH * M_KV, INNER, CD);

    // Attention (fp16 tensor cores)
    attn16_kernel<<<dim3(N_Q / 128, BATCH * HEADS), blk, ATTN_SMEM>>>();

    // out = O @ Wout + bout (fp32 in, tf32 mma, fp32 out)
    mma_gemm<0><<<dim3(QD / BN, (BATCH * N_Q) / BM), blk, GEMM_SMEM>>>(
        Ob, Wout, bout, out, BATCH * N_Q, QD, INNER);
}

// round 5
// speedup vs baseline: 5.7423x; 1.9505x over previous
#include <cuda_runtime.h>
#include <cuda_fp16.h>
#include <cstdint>
#include <math.h>

// Problem constants
#define BATCH   4
#define N_Q     2048
#define M_KV    1024
#define QD      1024
#define CD      768
#define HEADS   8
#define DHEAD   64
#define INNER   (HEADS * DHEAD)   // 512
#define ATT_SCALE 0.125f

// Device-global scratch (halves)
__device__ __half g_xh  [(size_t)BATCH * N_Q * QD];     // 8.4M
__device__ __half g_ctxh[(size_t)BATCH * M_KV * CD];    // 3.1M
__device__ __half g_Wqh [QD * INNER];
__device__ __half g_Wkh [CD * INNER];
__device__ __half g_Wvh [CD * INNER];
__device__ __half g_Wouth[INNER * QD];
__device__ __half g_Qh[(size_t)BATCH * N_Q * INNER];
__device__ __half g_Kh[(size_t)BATCH * M_KV * INNER];
__device__ __half g_Vh[(size_t)BATCH * M_KV * INNER];
__device__ __half g_Oh[(size_t)BATCH * N_Q * INNER];

__device__ __forceinline__ uint32_t smem_u32(const void* p) {
    uint32_t a;
    asm("{ .reg .u64 t; cvta.to.shared.u64 t, %1; cvt.u32.u64 %0, t; }"
        : "=r"(a) : "l"(p));
    return a;
}

__device__ __forceinline__ uint32_t pack_f16x2(float lo, float hi) {
    uint32_t r;
    asm("cvt.rn.f16x2.f32 %0, %1, %2;" : "=r"(r) : "f"(hi), "f"(lo));
    return r;
}

__device__ __forceinline__ void mma16816h(float c[4], const uint32_t a[4],
                                          const uint32_t b0, const uint32_t b1) {
    asm volatile(
        "mma.sync.aligned.m16n8k16.row.col.f32.f16.f16.f32 "
        "{%0,%1,%2,%3}, {%4,%5,%6,%7}, {%8,%9}, {%0,%1,%2,%3};"
        : "+f"(c[0]), "+f"(c[1]), "+f"(c[2]), "+f"(c[3])
        : "r"(a[0]), "r"(a[1]), "r"(a[2]), "r"(a[3]), "r"(b0), "r"(b1));
}

__device__ __forceinline__ void ldmx4(uint32_t r[4], uint32_t addr) {
    asm volatile("ldmatrix.sync.aligned.m8n8.x4.shared.b16 {%0,%1,%2,%3}, [%4];"
                 : "=r"(r[0]), "=r"(r[1]), "=r"(r[2]), "=r"(r[3]) : "r"(addr));
}
__device__ __forceinline__ void ldmx4t(uint32_t r[4], uint32_t addr) {
    asm volatile("ldmatrix.sync.aligned.m8n8.x4.trans.shared.b16 {%0,%1,%2,%3}, [%4];"
                 : "=r"(r[0]), "=r"(r[1]), "=r"(r[2]), "=r"(r[3]) : "r"(addr));
}

// ---------------------------------------------------------------------------
// f32 -> f16 conversion (n divisible by 4)
// ---------------------------------------------------------------------------
__global__ void __launch_bounds__(256) cvt_f16(const float* __restrict__ in,
                                               __half* __restrict__ out, int n4)
{
    const int i = blockIdx.x * 256 + threadIdx.x;
    if (i < n4) {
        const float4 v = ((const float4*)in)[i];
        uint2 h;
        h.x = pack_f16x2(v.x, v.y);
        h.y = pack_f16x2(v.z, v.w);
        ((uint2*)out)[i] = h;
    }
}

// ---------------------------------------------------------------------------
// fp16 mma.sync GEMM: C[M,N] = A[M,K] @ B[K,N] (+bias)
// A,B half. 128x128 tile, BK=32, 256 threads, 8 warps (2x4), warp 64x32.
// OUT16: C half; else C float (+fp32 bias).
// ---------------------------------------------------------------------------
#define BM 128
#define BN 128
#define BK 32
#define HASTR 40    // halves (80B rows: ldmatrix conflict-free)
#define HBSTR 136   // halves (272B rows)
#define HAS (BM * HASTR)   // 5120 halves
#define HBS (BK * HBSTR)   // 4352 halves
#define GEMM_SMEM ((2 * (HAS + HBS)) * 2)   // 37888 B

template <int OUT16>
__global__ void __launch_bounds__(256) hgemm(
    const __half* __restrict__ A, const __half* __restrict__ B,
    const float* __restrict__ bias, void* __restrict__ Cv,
    int M, int N, int K)
{
    extern __shared__ __half sh[];
    __half* As[2] = { sh, sh + HAS };
    __half* Bs[2] = { sh + 2 * HAS, sh + 2 * HAS + HBS };

    const int tid  = threadIdx.x;
    const int wid  = tid >> 5;
    const int lane = tid & 31;
    const int g  = lane >> 2;
    const int kq = lane & 3;
    const int warp_m = wid >> 2;   // 0..1
    const int warp_n = wid & 3;    // 0..3
    const int bm = blockIdx.y * BM;
    const int bn = blockIdx.x * BN;

    // gmem chunk-load mappings (uint4 = 8 halves)
    const int a_row[2] = { tid >> 2, (tid + 256) >> 2 };
    const int a_seg = tid & 3;
    const int b_row[2] = { tid >> 4, (tid + 256) >> 4 };
    const int b_seg = tid & 15;

    const uint32_t abase[2] = { smem_u32(As[0]), smem_u32(As[1]) };
    const uint32_t bbase[2] = { smem_u32(Bs[0]), smem_u32(Bs[1]) };

    uint4 aST[2], bST[2];
    float c[4][4][4];
#pragma unroll
    for (int mi = 0; mi < 4; mi++)
#pragma unroll
        for (int ni = 0; ni < 4; ni++)
#pragma unroll
            for (int t = 0; t < 4; t++) c[mi][ni][t] = 0.0f;

    const int NC = K / BK;

    // chunk 0
#pragma unroll
    for (int t = 0; t < 2; t++) {
        aST[t] = *(const uint4*)(A + (size_t)(bm + a_row[t]) * K + a_seg * 8);
        bST[t] = *(const uint4*)(B + (size_t)b_row[t] * N + bn + b_seg * 8);
    }
#pragma unroll
    for (int t = 0; t < 2; t++) {
        *(uint4*)&As[0][a_row[t] * HASTR + a_seg * 8] = aST[t];
        *(uint4*)&Bs[0][b_row[t] * HBSTR + b_seg * 8] = bST[t];
    }

    for (int kc = 0; kc < NC; kc++) {
        const int p = kc & 1;
        __syncthreads();

        if (kc + 1 < NC) {
            const int k0 = (kc + 1) * BK;
#pragma unroll
            for (int t = 0; t < 2; t++) {
                aST[t] = *(const uint4*)(A + (size_t)(bm + a_row[t]) * K + k0 + a_seg * 8);
                bST[t] = *(const uint4*)(B + (size_t)(k0 + b_row[t]) * N + bn + b_seg * 8);
            }
        }

#pragma unroll
        for (int ks = 0; ks < 2; ks++) {
            const int kk = ks * 16;
            uint32_t bf[2][4];
#pragma unroll
            for (int ng = 0; ng < 2; ng++) {
                const uint32_t addr = bbase[p] + (uint32_t)((
                    (kk + (lane & 15)) * HBSTR +
                    warp_n * 32 + ng * 16 + ((lane >> 4) << 3)) * 2);
                ldmx4t(bf[ng], addr);
            }
#pragma unroll
            for (int mi = 0; mi < 4; mi++) {
                uint32_t af[4];
                const uint32_t addr = abase[p] + (uint32_t)((
                    (warp_m * 64 + mi * 16 + (lane & 15)) * HASTR +
                    kk + ((lane >> 4) << 3)) * 2);
                ldmx4(af, addr);
                mma16816h(c[mi][0], af, bf[0][0], bf[0][1]);
                mma16816h(c[mi][1], af, bf[0][2], bf[0][3]);
                mma16816h(c[mi][2], af, bf[1][0], bf[1][1]);
                mma16816h(c[mi][3], af, bf[1][2], bf[1][3]);
            }
        }

        if (kc + 1 < NC) {
#pragma unroll
            for (int t = 0; t < 2; t++) {
                *(uint4*)&As[p ^ 1][a_row[t] * HASTR + a_seg * 8] = aST[t];
                *(uint4*)&Bs[p ^ 1][b_row[t] * HBSTR + b_seg * 8] = bST[t];
            }
        }
    }

    // epilogue: frag (mi,ni): rows g,g+8; cols 2*kq,2*kq+1
#pragma unroll
    for (int mi = 0; mi < 4; mi++) {
        const int row0 = bm + warp_m * 64 + mi * 16 + g;
#pragma unroll
        for (int ni = 0; ni < 4; ni++) {
            const int col = bn + warp_n * 32 + ni * 8 + 2 * kq;
            if (OUT16) {
                __half* Ch = (__half*)Cv;
                *(uint32_t*)(Ch + (size_t)row0 * N + col) =
                    pack_f16x2(c[mi][ni][0], c[mi][ni][1]);
                *(uint32_t*)(Ch + (size_t)(row0 + 8) * N + col) =
                    pack_f16x2(c[mi][ni][2], c[mi][ni][3]);
            } else {
                float* C = (float*)Cv;
                float2 v0 = make_float2(c[mi][ni][0], c[mi][ni][1]);
                float2 v1 = make_float2(c[mi][ni][2], c[mi][ni][3]);
                if (bias != nullptr) {
                    const float2 bv = *(const float2*)(bias + col);
                    v0.x += bv.x; v0.y += bv.y;
                    v1.x += bv.x; v1.y += bv.y;
                }
                *(float2*)(C + (size_t)row0 * N + col)       = v0;
                *(float2*)(C + (size_t)(row0 + 8) * N + col) = v1;
            }
        }
    }
}

// ---------------------------------------------------------------------------
// fp16 tensor-core flash attention (R4-proven), now writing O as half.
// ---------------------------------------------------------------------------
#define QSTR 88
#define ATTN_SMEM ((128 * QSTR + 2 * 64 * QSTR) * 2)

__global__ void __launch_bounds__(256) attn16_kernel()
{
    extern __shared__ __half sha[];
    __half* Qs = sha;
    __half* Ks = sha + 128 * QSTR;
    __half* Vs = sha + 192 * QSTR;

    const int tid  = threadIdx.x;
    const int wid  = tid >> 5;
    const int lane = tid & 31;
    const int qt   = blockIdx.x;
    const int bh   = blockIdx.y;
    const int b    = bh >> 3;
    const int h    = bh & 7;

    const __half* Qp = g_Qh + ((size_t)b * N_Q)  * INNER + h * DHEAD;
    const __half* Kp = g_Kh + ((size_t)b * M_KV) * INNER + h * DHEAD;
    const __half* Vp = g_Vh + ((size_t)b * M_KV) * INNER + h * DHEAD;
    __half*       Op = g_Oh + ((size_t)b * N_Q)  * INNER + h * DHEAD;

    for (int i = tid; i < 128 * 8; i += 256) {
        const int row = i >> 3;
        const int seg = i & 7;
        *(uint4*)&Qs[row * QSTR + seg * 8] =
            *(const uint4*)(Qp + (size_t)(qt * 128 + row) * INNER + seg * 8);
    }
    __syncthreads();

    const uint32_t qbase = smem_u32(Qs);
    const uint32_t kbase = smem_u32(Ks);
    const uint32_t vbase = smem_u32(Vs);
    uint32_t qa[4][4];
    {
        const int r0 = wid * 16;
#pragma unroll
        for (int t = 0; t < 4; t++) {
            const uint32_t addr = qbase +
                (uint32_t)(((r0 + (lane & 15)) * QSTR + t * 16 + ((lane >> 4) << 3)) * 2);
            ldmx4(qa[t], addr);
        }
    }

    float o[8][4];
#pragma unroll
    for (int j = 0; j < 8; j++)
#pragma unroll
        for (int t = 0; t < 4; t++) o[j][t] = 0.0f;
    float mrow[2] = { -1e30f, -1e30f };
    float lrow[2] = { 0.0f, 0.0f };

    const int ld_row[2] = { tid >> 3, (tid + 256) >> 3 };
    const int ld_seg = tid & 7;
    uint4 kpf[2], vpf[2];
#pragma unroll
    for (int t = 0; t < 2; t++) {
        kpf[t] = *(const uint4*)(Kp + (size_t)ld_row[t] * INNER + ld_seg * 8);
        vpf[t] = *(const uint4*)(Vp + (size_t)ld_row[t] * INNER + ld_seg * 8);
    }

    const int NCH = M_KV / 64;
    for (int c = 0; c < NCH; c++) {
#pragma unroll
        for (int t = 0; t < 2; t++) {
            *(uint4*)&Ks[ld_row[t] * QSTR + ld_seg * 8] = kpf[t];
            *(uint4*)&Vs[ld_row[t] * QSTR + ld_seg * 8] = vpf[t];
        }
        __syncthreads();

        if (c + 1 < NCH) {
            const size_t base = (size_t)(c + 1) * 64;
#pragma unroll
            for (int t = 0; t < 2; t++) {
                kpf[t] = *(const uint4*)(Kp + (base + ld_row[t]) * INNER + ld_seg * 8);
                vpf[t] = *(const uint4*)(Vp + (base + ld_row[t]) * INNER + ld_seg * 8);
            }
        }

        float sc[8][4];
#pragma unroll
        for (int n = 0; n < 8; n++)
#pragma unroll
            for (int t = 0; t < 4; t++) sc[n][t] = 0.0f;

#pragma unroll
        for (int np = 0; np < 4; np++) {
#pragma unroll
            for (int t = 0; t < 4; t++) {
                uint32_t kb[4];
                const uint32_t addr = kbase + (uint32_t)((
                    (16 * np + (lane & 7) + 8 * (lane >> 4)) * QSTR +
                    16 * t + 8 * ((lane >> 3) & 1)) * 2);
                ldmx4(kb, addr);
                mma16816h(sc[2 * np],     qa[t], kb[0], kb[1]);
                mma16816h(sc[2 * np + 1], qa[t], kb[2], kb[3]);
            }
        }

        float mx0 = -1e30f, mx1 = -1e30f;
#pragma unroll
        for (int n = 0; n < 8; n++) {
            mx0 = fmaxf(mx0, fmaxf(sc[n][0], sc[n][1]));
            mx1 = fmaxf(mx1, fmaxf(sc[n][2], sc[n][3]));
        }
        mx0 = fmaxf(mx0, __shfl_xor_sync(0xffffffffu, mx0, 1));
        mx0 = fmaxf(mx0, __shfl_xor_sync(0xffffffffu, mx0, 2));
        mx1 = fmaxf(mx1, __shfl_xor_sync(0xffffffffu, mx1, 1));
        mx1 = fmaxf(mx1, __shfl_xor_sync(0xffffffffu, mx1, 2));

        const float mn0 = fmaxf(mrow[0], mx0);
        const float mn1 = fmaxf(mrow[1], mx1);
        const float cr0 = __expf(ATT_SCALE * (mrow[0] - mn0));
        const float cr1 = __expf(ATT_SCALE * (mrow[1] - mn1));
        mrow[0] = mn0; mrow[1] = mn1;

        float rs0 = 0.0f, rs1 = 0.0f;
#pragma unroll
        for (int n = 0; n < 8; n++) {
            sc[n][0] = __expf(ATT_SCALE * (sc[n][0] - mn0));
            sc[n][1] = __expf(ATT_SCALE * (sc[n][1] - mn0));
            sc[n][2] = __expf(ATT_SCALE * (sc[n][2] - mn1));
            sc[n][3] = __expf(ATT_SCALE * (sc[n][3] - mn1));
            rs0 += sc[n][0] + sc[n][1];
            rs1 += sc[n][2] + sc[n][3];
        }
        rs0 += __shfl_xor_sync(0xffffffffu, rs0, 1);
        rs0 += __shfl_xor_sync(0xffffffffu, rs0, 2);
        rs1 += __shfl_xor_sync(0xffffffffu, rs1, 1);
        rs1 += __shfl_xor_sync(0xffffffffu, rs1, 2);
        lrow[0] = lrow[0] * cr0 + rs0;
        lrow[1] = lrow[1] * cr1 + rs1;

#pragma unroll
        for (int j = 0; j < 8; j++) {
            o[j][0] *= cr0; o[j][1] *= cr0;
            o[j][2] *= cr1; o[j][3] *= cr1;
        }

        uint32_t pa[4][4];
#pragma unroll
        for (int t = 0; t < 4; t++) {
            pa[t][0] = pack_f16x2(sc[2 * t][0],     sc[2 * t][1]);
            pa[t][1] = pack_f16x2(sc[2 * t][2],     sc[2 * t][3]);
            pa[t][2] = pack_f16x2(sc[2 * t + 1][0], sc[2 * t + 1][1]);
            pa[t][3] = pack_f16x2(sc[2 * t + 1][2], sc[2 * t + 1][3]);
        }

#pragma unroll
        for (int t = 0; t < 4; t++) {
#pragma unroll
            for (int jp = 0; jp < 4; jp++) {
                uint32_t vb[4];
                const uint32_t addr = vbase + (uint32_t)((
                    (16 * t + (lane & 15)) * QSTR +
                    16 * jp + ((lane >> 4) << 3)) * 2);
                ldmx4t(vb, addr);
                mma16816h(o[2 * jp],     pa[t], vb[0], vb[1]);
                mma16816h(o[2 * jp + 1], pa[t], vb[2], vb[3]);
            }
        }
        __syncthreads();
    }

    const float inv0 = 1.0f / lrow[0];
    const float inv1 = 1.0f / lrow[1];
    const int g  = lane >> 2;
    const int kq = lane & 3;
    const int row0 = qt * 128 + wid * 16 + g;
#pragma unroll
    for (int j = 0; j < 8; j++) {
        const int col = j * 8 + 2 * kq;
        *(uint32_t*)(Op + (size_t)row0 * INNER + col) =
            pack_f16x2(o[j][0] * inv0, o[j][1] * inv0);
        *(uint32_t*)(Op + (size_t)(row0 + 8) * INNER + col) =
            pack_f16x2(o[j][2] * inv1, o[j][3] * inv1);
    }
}

// ---------------------------------------------------------------------------
// kernel_launch
// ---------------------------------------------------------------------------
extern "C" void kernel_launch(void* const* d_in, const int* in_sizes, int n_in,
                              void* d_out, int out_size)
{
    const float* x    = (const float*)d_in[0];
    const float* ctx  = (const float*)d_in[1];
    const float* Wq   = (const float*)d_in[2];
    const float* Wk   = (const float*)d_in[3];
    const float* Wv   = (const float*)d_in[4];
    const float* Wout = (const float*)d_in[5];
    const float* bout = (const float*)d_in[6];
    float* out = (float*)d_out;

    __half *xh, *ctxh, *Wqh, *Wkh, *Wvh, *Wouth, *Qb, *Kb, *Vb, *Ob;
    cudaGetSymbolAddress((void**)&xh,   g_xh);
    cudaGetSymbolAddress((void**)&ctxh, g_ctxh);
    cudaGetSymbolAddress((void**)&Wqh,  g_Wqh);
    cudaGetSymbolAddress((void**)&Wkh,  g_Wkh);
    cudaGetSymbolAddress((void**)&Wvh,  g_Wvh);
    cudaGetSymbolAddress((void**)&Wouth,g_Wouth);
    cudaGetSymbolAddress((void**)&Qb,   g_Qh);
    cudaGetSymbolAddress((void**)&Kb,   g_Kh);
    cudaGetSymbolAddress((void**)&Vb,   g_Vh);
    cudaGetSymbolAddress((void**)&Ob,   g_Oh);

    cudaFuncSetAttribute(attn16_kernel,
                         cudaFuncAttributeMaxDynamicSharedMemorySize, ATTN_SMEM);

    const dim3 blk(256);

    // fp32 -> fp16 conversions
    {
        struct { const float* src; __half* dst; int n; } cv[6] = {
            { x,    xh,    BATCH * N_Q * QD },
            { ctx,  ctxh,  BATCH * M_KV * CD },
            { Wq,   Wqh,   QD * INNER },
            { Wk,   Wkh,   CD * INNER },
            { Wv,   Wvh,   CD * INNER },
            { Wout, Wouth, INNER * QD },
        };
        for (int i = 0; i < 6; i++) {
            const int n4 = cv[i].n / 4;
            cvt_f16<<<(n4 + 255) / 256, blk>>>(cv[i].src, cv[i].dst, n4);
        }
    }

    // Projections (fp16 in, fp16 out)
    hgemm<1><<<dim3(INNER / BN, (BATCH * N_Q) / BM), blk, GEMM_SMEM>>>(
        xh, Wqh, nullptr, Qb, BATCH * N_Q, INNER, QD);
    hgemm<1><<<dim3(INNER / BN, (BATCH * M_KV) / BM), blk, GEMM_SMEM>>>(
        ctxh, Wkh, nullptr, Kb, BATCH * M_KV, INNER, CD);
    hgemm<1><<<dim3(INNER / BN, (BATCH * M_KV) / BM), blk, GEMM_SMEM>>>(
        ctxh, Wvh, nullptr, Vb, BATCH * M_KV, INNER, CD);

    // Attention (fp16 tensor cores) -> O half
    attn16_kernel<<<dim3(N_Q / 128, BATCH * HEADS), blk, ATTN_SMEM>>>();

    // out = O @ Wout + bout (fp16 in, fp32 out)
    hgemm<0><<<dim3(QD / BN, (BATCH * N_Q) / BM), blk, GEMM_SMEM>>>(
        Ob, Wouth, bout, out, BATCH * N_Q, QD, INNER);
}

// round 6
// speedup vs baseline: 5.9058x; 1.0285x over previous
#include <cuda_runtime.h>
#include <cuda_fp16.h>
#include <cstdint>
#include <math.h>

// Problem constants
#define BATCH   4
#define N_Q     2048
#define M_KV    1024
#define QD      1024
#define CD      768
#define HEADS   8
#define DHEAD   64
#define INNER   (HEADS * DHEAD)   // 512
#define ATT_SCALE 0.125f

// Device-global scratch (halves)
__device__ __half g_xh  [(size_t)BATCH * N_Q * QD];
__device__ __half g_ctxh[(size_t)BATCH * M_KV * CD];
__device__ __half g_Wqh [QD * INNER];
__device__ __half g_Wkh [CD * INNER];
__device__ __half g_Wvh [CD * INNER];
__device__ __half g_Wouth[INNER * QD];
__device__ __half g_Qh[(size_t)BATCH * N_Q * INNER];
__device__ __half g_Kh[(size_t)BATCH * M_KV * INNER];
__device__ __half g_Vh[(size_t)BATCH * M_KV * INNER];
__device__ __half g_Oh[(size_t)BATCH * N_Q * INNER];

__device__ __forceinline__ uint32_t smem_u32(const void* p) {
    uint32_t a;
    asm("{ .reg .u64 t; cvta.to.shared.u64 t, %1; cvt.u32.u64 %0, t; }"
        : "=r"(a) : "l"(p));
    return a;
}

__device__ __forceinline__ uint32_t pack_f16x2(float lo, float hi) {
    uint32_t r;
    asm("cvt.rn.f16x2.f32 %0, %1, %2;" : "=r"(r) : "f"(hi), "f"(lo));
    return r;
}

__device__ __forceinline__ void mma16816h(float c[4], const uint32_t a[4],
                                          const uint32_t b0, const uint32_t b1) {
    asm volatile(
        "mma.sync.aligned.m16n8k16.row.col.f32.f16.f16.f32 "
        "{%0,%1,%2,%3}, {%4,%5,%6,%7}, {%8,%9}, {%0,%1,%2,%3};"
        : "+f"(c[0]), "+f"(c[1]), "+f"(c[2]), "+f"(c[3])
        : "r"(a[0]), "r"(a[1]), "r"(a[2]), "r"(a[3]), "r"(b0), "r"(b1));
}

__device__ __forceinline__ void ldmx4(uint32_t r[4], uint32_t addr) {
    asm volatile("ldmatrix.sync.aligned.m8n8.x4.shared.b16 {%0,%1,%2,%3}, [%4];"
                 : "=r"(r[0]), "=r"(r[1]), "=r"(r[2]), "=r"(r[3]) : "r"(addr));
}
__device__ __forceinline__ void ldmx4t(uint32_t r[4], uint32_t addr) {
    asm volatile("ldmatrix.sync.aligned.m8n8.x4.trans.shared.b16 {%0,%1,%2,%3}, [%4];"
                 : "=r"(r[0]), "=r"(r[1]), "=r"(r[2]), "=r"(r[3]) : "r"(addr));
}

__device__ __forceinline__ void cp16(uint32_t dst, const void* src) {
    asm volatile("cp.async.cg.shared.global [%0], [%1], 16;"
                 :: "r"(dst), "l"(src) : "memory");
}
#define CP_COMMIT() asm volatile("cp.async.commit_group;" ::: "memory")
#define CP_WAIT(n)  asm volatile("cp.async.wait_group %0;" :: "n"(n) : "memory")

// ---------------------------------------------------------------------------
// f32 -> f16 conversion
// ---------------------------------------------------------------------------
__global__ void __launch_bounds__(256) cvt_f16(const float* __restrict__ in,
                                               __half* __restrict__ out, int n4)
{
    const int i = blockIdx.x * 256 + threadIdx.x;
    if (i < n4) {
        const float4 v = ((const float4*)in)[i];
        uint2 h;
        h.x = pack_f16x2(v.x, v.y);
        h.y = pack_f16x2(v.z, v.w);
        ((uint2*)out)[i] = h;
    }
}

// ---------------------------------------------------------------------------
// fp16 mma GEMM with 3-stage cp.async pipeline.
// C[M,N] = A[M,K] @ B[K,N] (+bias). 128x128 tile, BK=32, 256 threads.
// ---------------------------------------------------------------------------
#define BM 128
#define BN 128
#define BK 32
#define HASTR 40
#define HBSTR 136
#define HAS (BM * HASTR)                 // 5120 halves
#define HBS (BK * HBSTR)                 // 4352 halves
#define NSTG 3
#define A_STG_B (HAS * 2)                // bytes per A stage
#define B_STG_B (HBS * 2)
#define GEMM_SMEM (NSTG * (A_STG_B + B_STG_B))   // 56832 B

template <int OUT16>
__global__ void __launch_bounds__(256) hgemm(
    const __half* __restrict__ A, const __half* __restrict__ B,
    const float* __restrict__ bias, void* __restrict__ Cv,
    int M, int N, int K)
{
    extern __shared__ __half sh[];
    const uint32_t sA = smem_u32(sh);
    const uint32_t sB = sA + NSTG * A_STG_B;

    const int tid  = threadIdx.x;
    const int wid  = tid >> 5;
    const int lane = tid & 31;
    const int g  = lane >> 2;
    const int kq = lane & 3;
    const int warp_m = wid >> 2;
    const int warp_n = wid & 3;
    const int bm = blockIdx.y * BM;
    const int bn = blockIdx.x * BN;

    const int a_row[2] = { tid >> 2, (tid + 256) >> 2 };
    const int a_seg = tid & 3;
    const int b_row[2] = { tid >> 4, (tid + 256) >> 4 };
    const int b_seg = tid & 15;

    // precomputed smem byte offsets for this thread's cp.async targets
    const uint32_t a_dst[2] = {
        (uint32_t)((a_row[0] * HASTR + a_seg * 8) * 2),
        (uint32_t)((a_row[1] * HASTR + a_seg * 8) * 2) };
    const uint32_t b_dst[2] = {
        (uint32_t)((b_row[0] * HBSTR + b_seg * 8) * 2),
        (uint32_t)((b_row[1] * HBSTR + b_seg * 8) * 2) };

    float c[4][4][4];
#pragma unroll
    for (int mi = 0; mi < 4; mi++)
#pragma unroll
        for (int ni = 0; ni < 4; ni++)
#pragma unroll
            for (int t = 0; t < 4; t++) c[mi][ni][t] = 0.0f;

    const int NC = K / BK;

    auto issue = [&](int kc, int stg) {
        const int k0 = kc * BK;
        const uint32_t aS = sA + stg * A_STG_B;
        const uint32_t bS = sB + stg * B_STG_B;
#pragma unroll
        for (int t = 0; t < 2; t++)
            cp16(aS + a_dst[t], A + (size_t)(bm + a_row[t]) * K + k0 + a_seg * 8);
#pragma unroll
        for (int t = 0; t < 2; t++)
            cp16(bS + b_dst[t], B + (size_t)(k0 + b_row[t]) * N + bn + b_seg * 8);
    };

    // prologue: stages 0..NSTG-2
    issue(0, 0); CP_COMMIT();
    issue(1, 1); CP_COMMIT();

    int stg = 0;
    for (int kc = 0; kc < NC; kc++) {
        CP_WAIT(NSTG - 2);
        __syncthreads();

        const int knext = kc + NSTG - 1;
        if (knext < NC) {
            int ns = stg + NSTG - 1; if (ns >= NSTG) ns -= NSTG;
            issue(knext, ns);
        }
        CP_COMMIT();

        const uint32_t aS = sA + stg * A_STG_B;
        const uint32_t bS = sB + stg * B_STG_B;
#pragma unroll
        for (int ks = 0; ks < 2; ks++) {
            const int kk = ks * 16;
            uint32_t bf[2][4];
#pragma unroll
            for (int ng = 0; ng < 2; ng++) {
                const uint32_t addr = bS + (uint32_t)((
                    (kk + (lane & 15)) * HBSTR +
                    warp_n * 32 + ng * 16 + ((lane >> 4) << 3)) * 2);
                ldmx4t(bf[ng], addr);
            }
#pragma unroll
            for (int mi = 0; mi < 4; mi++) {
                uint32_t af[4];
                const uint32_t addr = aS + (uint32_t)((
                    (warp_m * 64 + mi * 16 + (lane & 15)) * HASTR +
                    kk + ((lane >> 4) << 3)) * 2);
                ldmx4(af, addr);
                mma16816h(c[mi][0], af, bf[0][0], bf[0][1]);
                mma16816h(c[mi][1], af, bf[0][2], bf[0][3]);
                mma16816h(c[mi][2], af, bf[1][0], bf[1][1]);
                mma16816h(c[mi][3], af, bf[1][2], bf[1][3]);
            }
        }
        if (++stg == NSTG) stg = 0;
    }

#pragma unroll
    for (int mi = 0; mi < 4; mi++) {
        const int row0 = bm + warp_m * 64 + mi * 16 + g;
#pragma unroll
        for (int ni = 0; ni < 4; ni++) {
            const int col = bn + warp_n * 32 + ni * 8 + 2 * kq;
            if (OUT16) {
                __half* Ch = (__half*)Cv;
                *(uint32_t*)(Ch + (size_t)row0 * N + col) =
                    pack_f16x2(c[mi][ni][0], c[mi][ni][1]);
                *(uint32_t*)(Ch + (size_t)(row0 + 8) * N + col) =
                    pack_f16x2(c[mi][ni][2], c[mi][ni][3]);
            } else {
                float* C = (float*)Cv;
                float2 v0 = make_float2(c[mi][ni][0], c[mi][ni][1]);
                float2 v1 = make_float2(c[mi][ni][2], c[mi][ni][3]);
                if (bias != nullptr) {
                    const float2 bv = *(const float2*)(bias + col);
                    v0.x += bv.x; v0.y += bv.y;
                    v1.x += bv.x; v1.y += bv.y;
                }
                *(float2*)(C + (size_t)row0 * N + col)       = v0;
                *(float2*)(C + (size_t)(row0 + 8) * N + col) = v1;
            }
        }
    }
}

// ---------------------------------------------------------------------------
// fp16 flash attention with 3-stage cp.async K/V pipeline.
// ---------------------------------------------------------------------------
#define QSTR 88
#define Q_BYTES (128 * QSTR * 2)            // 22528
#define KV_STG_B (128 * QSTR * 2)           // K(64)+V(64) per stage = 22528
#define ATTN_SMEM (Q_BYTES + NSTG * KV_STG_B)   // 90112 B

__global__ void __launch_bounds__(256) attn16_kernel()
{
    extern __shared__ __half sha[];
    __half* Qs = sha;
    const uint32_t qbase = smem_u32(Qs);
    const uint32_t kv0   = qbase + Q_BYTES;

    const int tid  = threadIdx.x;
    const int wid  = tid >> 5;
    const int lane = tid & 31;
    const int qt   = blockIdx.x;
    const int bh   = blockIdx.y;
    const int b    = bh >> 3;
    const int h    = bh & 7;

    const __half* Qp = g_Qh + ((size_t)b * N_Q)  * INNER + h * DHEAD;
    const __half* Kp = g_Kh + ((size_t)b * M_KV) * INNER + h * DHEAD;
    const __half* Vp = g_Vh + ((size_t)b * M_KV) * INNER + h * DHEAD;
    __half*       Op = g_Oh + ((size_t)b * N_Q)  * INNER + h * DHEAD;

    // K/V cp.async mapping: per chunk, 2 x 16B per tensor per thread
    const int ld_row[2] = { tid >> 3, (tid + 256) >> 3 };
    const int ld_seg = tid & 7;
    const uint32_t kv_dst[2] = {
        (uint32_t)((ld_row[0] * QSTR + ld_seg * 8) * 2),
        (uint32_t)((ld_row[1] * QSTR + ld_seg * 8) * 2) };

    auto issue_kv = [&](int ch, int stg) {
        const uint32_t kS = kv0 + stg * KV_STG_B;
        const uint32_t vS = kS + 64 * QSTR * 2;
        const size_t base = (size_t)ch * 64;
#pragma unroll
        for (int t = 0; t < 2; t++) {
            cp16(kS + kv_dst[t], Kp + (base + ld_row[t]) * INNER + ld_seg * 8);
            cp16(vS + kv_dst[t], Vp + (base + ld_row[t]) * INNER + ld_seg * 8);
        }
    };

    // Q tile -> smem (synchronous, once)
    for (int i = tid; i < 128 * 8; i += 256) {
        const int row = i >> 3;
        const int seg = i & 7;
        *(uint4*)&Qs[row * QSTR + seg * 8] =
            *(const uint4*)(Qp + (size_t)(qt * 128 + row) * INNER + seg * 8);
    }

    issue_kv(0, 0); CP_COMMIT();
    issue_kv(1, 1); CP_COMMIT();
    __syncthreads();

    // Q a-frags
    uint32_t qa[4][4];
    {
        const int r0 = wid * 16;
#pragma unroll
        for (int t = 0; t < 4; t++) {
            const uint32_t addr = qbase +
                (uint32_t)(((r0 + (lane & 15)) * QSTR + t * 16 + ((lane >> 4) << 3)) * 2);
            ldmx4(qa[t], addr);
        }
    }

    float o[8][4];
#pragma unroll
    for (int j = 0; j < 8; j++)
#pragma unroll
        for (int t = 0; t < 4; t++) o[j][t] = 0.0f;
    float mrow[2] = { -1e30f, -1e30f };
    float lrow[2] = { 0.0f, 0.0f };

    const int NCH = M_KV / 64;
    int stg = 0;
    for (int c = 0; c < NCH; c++) {
        CP_WAIT(NSTG - 2);
        __syncthreads();

        const int cnext = c + NSTG - 1;
        if (cnext < NCH) {
            int ns = stg + NSTG - 1; if (ns >= NSTG) ns -= NSTG;
            issue_kv(cnext, ns);
        }
        CP_COMMIT();

        const uint32_t kS = kv0 + stg * KV_STG_B;
        const uint32_t vS = kS + 64 * QSTR * 2;

        // S = Q @ K^T
        float sc[8][4];
#pragma unroll
        for (int n = 0; n < 8; n++)
#pragma unroll
            for (int t = 0; t < 4; t++) sc[n][t] = 0.0f;

#pragma unroll
        for (int np = 0; np < 4; np++) {
#pragma unroll
            for (int t = 0; t < 4; t++) {
                uint32_t kb[4];
                const uint32_t addr = kS + (uint32_t)((
                    (16 * np + (lane & 7) + 8 * (lane >> 4)) * QSTR +
                    16 * t + 8 * ((lane >> 3) & 1)) * 2);
                ldmx4(kb, addr);
                mma16816h(sc[2 * np],     qa[t], kb[0], kb[1]);
                mma16816h(sc[2 * np + 1], qa[t], kb[2], kb[3]);
            }
        }

        // online softmax
        float mx0 = -1e30f, mx1 = -1e30f;
#pragma unroll
        for (int n = 0; n < 8; n++) {
            mx0 = fmaxf(mx0, fmaxf(sc[n][0], sc[n][1]));
            mx1 = fmaxf(mx1, fmaxf(sc[n][2], sc[n][3]));
        }
        mx0 = fmaxf(mx0, __shfl_xor_sync(0xffffffffu, mx0, 1));
        mx0 = fmaxf(mx0, __shfl_xor_sync(0xffffffffu, mx0, 2));
        mx1 = fmaxf(mx1, __shfl_xor_sync(0xffffffffu, mx1, 1));
        mx1 = fmaxf(mx1, __shfl_xor_sync(0xffffffffu, mx1, 2));

        const float mn0 = fmaxf(mrow[0], mx0);
        const float mn1 = fmaxf(mrow[1], mx1);
        const float cr0 = __expf(ATT_SCALE * (mrow[0] - mn0));
        const float cr1 = __expf(ATT_SCALE * (mrow[1] - mn1));
        mrow[0] = mn0; mrow[1] = mn1;

        float rs0 = 0.0f, rs1 = 0.0f;
#pragma unroll
        for (int n = 0; n < 8; n++) {
            sc[n][0] = __expf(ATT_SCALE * (sc[n][0] - mn0));
            sc[n][1] = __expf(ATT_SCALE * (sc[n][1] - mn0));
            sc[n][2] = __expf(ATT_SCALE * (sc[n][2] - mn1));
            sc[n][3] = __expf(ATT_SCALE * (sc[n][3] - mn1));
            rs0 += sc[n][0] + sc[n][1];
            rs1 += sc[n][2] + sc[n][3];
        }
        rs0 += __shfl_xor_sync(0xffffffffu, rs0, 1);
        rs0 += __shfl_xor_sync(0xffffffffu, rs0, 2);
        rs1 += __shfl_xor_sync(0xffffffffu, rs1, 1);
        rs1 += __shfl_xor_sync(0xffffffffu, rs1, 2);
        lrow[0] = lrow[0] * cr0 + rs0;
        lrow[1] = lrow[1] * cr1 + rs1;

#pragma unroll
        for (int j = 0; j < 8; j++) {
            o[j][0] *= cr0; o[j][1] *= cr0;
            o[j][2] *= cr1; o[j][3] *= cr1;
        }

        uint32_t pa[4][4];
#pragma unroll
        for (int t = 0; t < 4; t++) {
            pa[t][0] = pack_f16x2(sc[2 * t][0],     sc[2 * t][1]);
            pa[t][1] = pack_f16x2(sc[2 * t][2],     sc[2 * t][3]);
            pa[t][2] = pack_f16x2(sc[2 * t + 1][0], sc[2 * t + 1][1]);
            pa[t][3] = pack_f16x2(sc[2 * t + 1][2], sc[2 * t + 1][3]);
        }

        // O += P @ V
#pragma unroll
        for (int t = 0; t < 4; t++) {
#pragma unroll
            for (int jp = 0; jp < 4; jp++) {
                uint32_t vb[4];
                const uint32_t addr = vS + (uint32_t)((
                    (16 * t + (lane & 15)) * QSTR +
                    16 * jp + ((lane >> 4) << 3)) * 2);
                ldmx4t(vb, addr);
                mma16816h(o[2 * jp],     pa[t], vb[0], vb[1]);
                mma16816h(o[2 * jp + 1], pa[t], vb[2], vb[3]);
            }
        }
        if (++stg == NSTG) stg = 0;
    }

    const float inv0 = 1.0f / lrow[0];
    const float inv1 = 1.0f / lrow[1];
    const int g  = lane >> 2;
    const int kq = lane & 3;
    const int row0 = qt * 128 + wid * 16 + g;
#pragma unroll
    for (int j = 0; j < 8; j++) {
        const int col = j * 8 + 2 * kq;
        *(uint32_t*)(Op + (size_t)row0 * INNER + col) =
            pack_f16x2(o[j][0] * inv0, o[j][1] * inv0);
        *(uint32_t*)(Op + (size_t)(row0 + 8) * INNER + col) =
            pack_f16x2(o[j][2] * inv1, o[j][3] * inv1);
    }
}

// ---------------------------------------------------------------------------
// kernel_launch
// ---------------------------------------------------------------------------
extern "C" void kernel_launch(void* const* d_in, const int* in_sizes, int n_in,
                              void* d_out, int out_size)
{
    const float* x    = (const float*)d_in[0];
    const float* ctx  = (const float*)d_in[1];
    const float* Wq   = (const float*)d_in[2];
    const float* Wk   = (const float*)d_in[3];
    const float* Wv   = (const float*)d_in[4];
    const float* Wout = (const float*)d_in[5];
    const float* bout = (const float*)d_in[6];
    float* out = (float*)d_out;

    __half *xh, *ctxh, *Wqh, *Wkh, *Wvh, *Wouth, *Qb, *Kb, *Vb, *Ob;
    cudaGetSymbolAddress((void**)&xh,   g_xh);
    cudaGetSymbolAddress((void**)&ctxh, g_ctxh);
    cudaGetSymbolAddress((void**)&Wqh,  g_Wqh);
    cudaGetSymbolAddress((void**)&Wkh,  g_Wkh);
    cudaGetSymbolAddress((void**)&Wvh,  g_Wvh);
    cudaGetSymbolAddress((void**)&Wouth,g_Wouth);
    cudaGetSymbolAddress((void**)&Qb,   g_Qh);
    cudaGetSymbolAddress((void**)&Kb,   g_Kh);
    cudaGetSymbolAddress((void**)&Vb,   g_Vh);
    cudaGetSymbolAddress((void**)&Ob,   g_Oh);

    cudaFuncSetAttribute(hgemm<0>,
                         cudaFuncAttributeMaxDynamicSharedMemorySize, GEMM_SMEM);
    cudaFuncSetAttribute(hgemm<1>,
                         cudaFuncAttributeMaxDynamicSharedMemorySize, GEMM_SMEM);
    cudaFuncSetAttribute(attn16_kernel,
                         cudaFuncAttributeMaxDynamicSharedMemorySize, ATTN_SMEM);

    const dim3 blk(256);

    // fp32 -> fp16 conversions
    {
        struct { const float* src; __half* dst; int n; } cv[6] = {
            { x,    xh,    BATCH * N_Q * QD },
            { ctx,  ctxh,  BATCH * M_KV * CD },
            { Wq,   Wqh,   QD * INNER },
            { Wk,   Wkh,   CD * INNER },
            { Wv,   Wvh,   CD * INNER },
            { Wout, Wouth, INNER * QD },
        };
        for (int i = 0; i < 6; i++) {
            const int n4 = cv[i].n / 4;
            cvt_f16<<<(n4 + 255) / 256, blk>>>(cv[i].src, cv[i].dst, n4);
        }
    }

    // Projections
    hgemm<1><<<dim3(INNER / BN, (BATCH * N_Q) / BM), blk, GEMM_SMEM>>>(
        xh, Wqh, nullptr, Qb, BATCH * N_Q, INNER, QD);
    hgemm<1><<<dim3(INNER / BN, (BATCH * M_KV) / BM), blk, GEMM_SMEM>>>(
        ctxh, Wkh, nullptr, Kb, BATCH * M_KV, INNER, CD);
    hgemm<1><<<dim3(INNER / BN, (BATCH * M_KV) / BM), blk, GEMM_SMEM>>>(
        ctxh, Wvh, nullptr, Vb, BATCH * M_KV, INNER, CD);

    // Attention
    attn16_kernel<<<dim3(N_Q / 128, BATCH * HEADS), blk, ATTN_SMEM>>>();

    // out = O @ Wout + bout
    hgemm<0><<<dim3(QD / BN, (BATCH * N_Q) / BM), blk, GEMM_SMEM>>>(
        Ob, Wouth, bout, out, BATCH * N_Q, QD, INNER);
}